// round 16
// baseline (speedup 1.0000x reference)
#include <cuda_runtime.h>
#include <cuda_fp16.h>
#include <cstdint>
#include <math.h>

// ===========================================================================
// StyleGAN2 block. R16: upsample + conv0 + conv1 all in ONE 4608-block kernel
// with flag-based dependencies (up rows -> conv0 tiles -> conv1 tiles).
// mma.sync fp16 (1 MMA/k-step), 4 CTAs/SM, to_rgb fused in layer-1 epilogue.
// Output: [rgb_out (8*3*64*64)] ++ [x (8*512*64*64)], fp32.
// ===========================================================================

#define Bn 8
#define Cn 512
#define HIN 32
#define PIX 4096
#define XELEMS (Bn*Cn*PIX)
#define RGBELEMS (Bn*3*PIX)
#define PADHW 66
#define PADCELLS (PADHW*PADHW)

// smem layout (bytes from dynamic smem base)
#define I_BUF   33792            // 4 rows * 66 cells * 128B (fp16), single
#define W_BASE  33792
#define W_STAGE 8192             // 64oc x 128B
#define N_WSTG  2
#define DSMEM   (W_BASE + N_WSTG*W_STAGE)   // 50176

// ---------------- device scratch (allocation-free rule) -------------------
__device__ __half g_xa[(size_t)Bn*PADCELLS*Cn];
__device__ __half g_xb[(size_t)Bn*PADCELLS*Cn];
__device__ __half g_wt0[9*Cn*Cn];
__device__ __half g_wt1[9*Cn*Cn];
__device__ float g_s0[Bn*Cn], g_s1[Bn*Cn], g_s2[Bn*Cn];
__device__ float g_d0[Bn*Cn], g_d1[Bn*Cn];
__device__ float g_wsq0[Cn*Cn], g_wsq1[Cn*Cn];
__device__ int   g_flag[256];    // octiles completed per (b*32 + ytile)
__device__ int   g_upflag[512];  // upsample row done per (b*64 + y)

// ---------------- helpers --------------------------------------------------
__device__ __forceinline__ uint32_t smem_u32(const void* p) {
    uint32_t a;
    asm("{ .reg .u64 t; cvta.to.shared.u64 t, %1; cvt.u32.u64 %0, t; }"
        : "=r"(a) : "l"(p));
    return a;
}
__device__ __forceinline__ void ldsm_x4(uint32_t* r, uint32_t addr) {
    asm volatile("ldmatrix.sync.aligned.m8n8.x4.shared.b16 {%0,%1,%2,%3}, [%4];"
        : "=r"(r[0]), "=r"(r[1]), "=r"(r[2]), "=r"(r[3]) : "r"(addr));
}
__device__ __forceinline__ void mma_f16(float* c, const uint32_t* a,
                                        const uint32_t* b) {
    asm volatile(
        "mma.sync.aligned.m16n8k16.row.col.f32.f16.f16.f32 "
        "{%0,%1,%2,%3},{%4,%5,%6,%7},{%8,%9},{%0,%1,%2,%3};"
        : "+f"(c[0]), "+f"(c[1]), "+f"(c[2]), "+f"(c[3])
        : "r"(a[0]), "r"(a[1]), "r"(a[2]), "r"(a[3]), "r"(b[0]), "r"(b[1]));
}
__device__ __forceinline__ void cp16(uint32_t dst, const void* src) {
    asm volatile("cp.async.cg.shared.global [%0], [%1], 16;"
        :: "r"(dst), "l"(src));
}
#define CP_COMMIT() asm volatile("cp.async.commit_group;" ::: "memory")
#define CP_WAIT0()  asm volatile("cp.async.wait_group 0;" ::: "memory")

// ---------------------------------------------------------------------------
// fused prep: styles + wsq + wprep + halo-zero + outRGB init + flag zero
// ---------------------------------------------------------------------------
#define N_STY (3*Bn*Cn)
#define N_WSQ (2*Cn*Cn)
#define N_WPR (2*9*Cn*Cn)
#define N_ZER (Bn*260*256)
#define N_RGBI RGBELEMS
#define N_FLG (256 + 512)
#define N_PREP (N_STY + N_WSQ + N_WPR + N_ZER + N_RGBI + N_FLG)

__global__ void k_prep(const float* __restrict__ w,
                       const float* __restrict__ sW0, const float* __restrict__ sB0,
                       const float* __restrict__ sW1, const float* __restrict__ sB1,
                       const float* __restrict__ sW2, const float* __restrict__ sB2,
                       const float* __restrict__ w0, const float* __restrict__ w1,
                       const float* __restrict__ rgb, const float* __restrict__ rgbB,
                       float* __restrict__ outRGB)
{
    int idx = blockIdx.x * blockDim.x + threadIdx.x;
    if (idx < N_STY) {
        int which = idx / (Bn * Cn);
        int rem   = idx % (Bn * Cn);
        int b = rem / Cn, c = rem % Cn;
        const float* sW = (which == 0) ? sW0 : (which == 1) ? sW1 : sW2;
        const float* sB = (which == 0) ? sB0 : (which == 1) ? sB1 : sB2;
        const float* wr = w + b * Cn;
        const float* sr = sW + c * Cn;
        float acc = 0.f;
        #pragma unroll 8
        for (int k = 0; k < Cn; ++k) acc += wr[k] * sr[k];
        acc += sB[c];
        ((which == 0) ? g_s0 : (which == 1) ? g_s1 : g_s2)[b * Cn + c] = acc;
        return;
    }
    idx -= N_STY;
    if (idx < N_WSQ) {
        const float* W = (idx < Cn * Cn) ? w0 : w1;
        float* out     = (idx < Cn * Cn) ? g_wsq0 : g_wsq1;
        int e = idx & (Cn * Cn - 1);
        const float* p = W + (size_t)e * 9;
        float a = 0.f;
        #pragma unroll
        for (int t = 0; t < 9; ++t) a += p[t] * p[t];
        out[e] = a;
        return;
    }
    idx -= N_WSQ;
    if (idx < N_WPR) {
        int layer = idx / (9 * Cn * Cn);
        int r = idx % (9 * Cn * Cn);
        int tap = r / (Cn * Cn);
        int rr = r % (Cn * Cn);
        int o = rr >> 9, i = rr & 511;
        const float* W = layer ? w1 : w0;
        float v = W[((size_t)o * Cn + i) * 9 + tap];
        size_t a = ((size_t)tap * Cn + o) * Cn + i;
        (layer ? g_wt1 : g_wt0)[a] = __float2half_rn(v);
        return;
    }
    idx -= N_WPR;
    if (idx < N_ZER) {
        int c2 = idx & 255;
        int cell = (idx >> 8) % 260;
        int b = (idx >> 8) / 260;
        int y, x;
        if (cell < 66)       { y = 0;  x = cell; }
        else if (cell < 132) { y = 65; x = cell - 66; }
        else { int r = cell - 132; y = 1 + (r & 63); x = (r >> 6) ? 65 : 0; }
        size_t a = ((((size_t)b * PADHW + y) * PADHW + x) * Cn) / 2 + c2;
        ((uint32_t*)g_xa)[a] = 0u;
        ((uint32_t*)g_xb)[a] = 0u;
        return;
    }
    idx -= N_ZER;
    if (idx < N_RGBI) {
        int X = idx & 63;
        int Y = (idx >> 6) & 63;
        int br = idx >> 12;
        int r = br % 3;
        int yl = (Y - 1) >> 1; int yu = yl + 1;
        float wyu = (Y & 1) ? 0.25f : 0.75f;
        yl = max(yl, 0); yu = min(yu, HIN - 1);
        int xl = (X - 1) >> 1; int xu = xl + 1;
        float wxu = (X & 1) ? 0.25f : 0.75f;
        xl = max(xl, 0); xu = min(xu, HIN - 1);
        const float* p = rgb + (size_t)br * (HIN * HIN);
        float up = (1.f - wyu) * ((1.f - wxu) * p[yl*HIN+xl] + wxu * p[yl*HIN+xu])
                 +         wyu * ((1.f - wxu) * p[yu*HIN+xl] + wxu * p[yu*HIN+xu]);
        outRGB[idx] = up + rgbB[r];
        return;
    }
    idx -= N_RGBI;
    if (idx < 256) { g_flag[idx] = 0; return; }
    idx -= 256;
    if (idx < 512) g_upflag[idx] = 0;
}

__global__ void k_demod()
{
    int idx = blockIdx.x * blockDim.x + threadIdx.x;
    if (idx >= 2 * Bn * Cn) return;
    int which = idx / (Bn * Cn);
    int rem   = idx % (Bn * Cn);
    int b = rem / Cn, o = rem % Cn;
    const float* wsq = which ? g_wsq1 : g_wsq0;
    const float* s   = which ? g_s1 : g_s0;
    const float* wr = wsq + o * Cn;
    const float* sr = s + b * Cn;
    float acc = 0.f;
    #pragma unroll 8
    for (int k = 0; k < Cn; ++k) { float sv = sr[k]; acc += wr[k] * sv * sv; }
    (which ? g_d1 : g_d0)[b * Cn + o] = rsqrtf(acc + 1e-8f);
}

// ---------------------------------------------------------------------------
// conv staging (128 threads)
// ---------------------------------------------------------------------------
__device__ __forceinline__ void stage_w(
    uint32_t wbase, int stg, const __half* __restrict__ wp,
    int o0, int tap, int ic0, int tid)
{
    const uint32_t base = wbase + stg * W_STAGE;
    #pragma unroll
    for (int k = 0; k < 4; ++k) {
        int s = tid + (k << 7);
        int r = s >> 3, g = s & 7;
        const __half* src = wp + ((size_t)tap * Cn + o0 + r) * Cn + ic0 + g * 8;
        uint32_t off = (uint32_t)((r << 7) + (g << 4));
        off ^= (off >> 3) & 0x70;
        cp16(base + off, src);
    }
}

__device__ __forceinline__ void stage_input_full(
    uint32_t ibase, const __half* __restrict__ x,
    int b, int y0, int ic0, int tid)
{
    for (int idx = tid; idx < 2112; idx += 128) {
        int cell = idx >> 3, g = idx & 7;
        int r = cell / 66, xx = cell - r * 66;
        const __half* src = x
            + (((size_t)b * PADHW + y0 + r) * PADHW + xx) * Cn + ic0 + g * 8;
        uint32_t off = (uint32_t)((cell << 7) + (g << 4));
        off ^= (off >> 3) & 0x70;
        cp16(ibase + off, src);
    }
}

// ---------------------------------------------------------------------------
// mega kernel: blocks [0,512) upsample rows; [512,2560) layer0; [2560,4608)
// layer1. Conv tile = 64oc x 128px; 128 threads, 4 warps 2m x 2n; 4 CTAs/SM.
// ---------------------------------------------------------------------------
__global__ void __launch_bounds__(128, 4) k_mega(
    const float* __restrict__ maps,
    const __half* __restrict__ xa_c, __half* __restrict__ xa_p,
    const __half* __restrict__ xb_c, __half* __restrict__ xb_p,
    const __half* __restrict__ wt0, const __half* __restrict__ wt1,
    const float* __restrict__ d0,  const float* __restrict__ d1,
    const float* __restrict__ bias0, const float* __restrict__ bias1,
    const float* __restrict__ ns0, const float* __restrict__ ns1,
    const float* __restrict__ noise0, const float* __restrict__ noise1,
    const float* __restrict__ s1,
    float* __restrict__ outX,
    const float* __restrict__ rgbW,
    const float* __restrict__ s2,
    float* __restrict__ outRGB)
{
    extern __shared__ __align__(16) char dsm[];
    const int tid = threadIdx.x;

    // ================= upsample blocks =================
    if (blockIdx.x < 512) {
        unsigned short* tile = (unsigned short*)dsm;  // [32][65]
        const int b = blockIdx.x >> 6, y = blockIdx.x & 63;

        int yl = (y - 1) >> 1, yu = yl + 1;
        float wyu = (y & 1) ? 0.25f : 0.75f;
        yl = max(yl, 0); yu = min(yu, HIN - 1);

        for (int c0 = 0; c0 < Cn; c0 += 32) {
            #pragma unroll
            for (int k = 0; k < 16; ++k) {
                int e = tid + (k << 7);
                int c = e >> 6, x = e & 63;
                int xl = (x - 1) >> 1, xu = xl + 1;
                float wxu = (x & 1) ? 0.25f : 0.75f;
                xl = max(xl, 0); xu = min(xu, HIN - 1);
                const float* p = maps + (size_t)(b * Cn + c0 + c) * (HIN * HIN);
                float v = (1.f - wyu) * ((1.f - wxu) * p[yl*HIN+xl] + wxu * p[yl*HIN+xu])
                        +         wyu * ((1.f - wxu) * p[yu*HIN+xl] + wxu * p[yu*HIN+xu]);
                v *= g_s0[b * Cn + c0 + c];
                tile[c * 65 + x] = __half_as_ushort(__float2half_rn(v));
            }
            __syncthreads();
            #pragma unroll
            for (int k = 0; k < 16; ++k) {
                int e = tid + (k << 7);
                int x = e >> 5, c = e & 31;
                size_t a = (((size_t)b * PADHW + y + 1) * PADHW + x + 1) * Cn + c0 + c;
                xa_p[a] = __ushort_as_half(tile[c * 65 + x]);
            }
            __syncthreads();
        }
        __threadfence();
        __syncthreads();
        if (tid == 0) atomicExch(&g_upflag[(b << 6) + y], 1);
        return;
    }

    // ================= conv blocks =================
    const uint32_t ib = smem_u32(dsm);
    const uint32_t wb = ib + W_BASE;
    const int lane = tid & 31, wid = tid >> 5;
    const int mw = wid >> 1, nwp = wid & 1;

    const int vt = blockIdx.x - 512;
    const int layer = vt >> 11;
    const int t = vt & 2047;
    const int o0 = (t & 7) * 64;
    const int nt = t >> 3;                 // b*32 + ytile
    const int b  = nt >> 5;
    const int yt = nt & 31;
    const int y0 = yt * 2;

    const __half* xin = layer ? xb_c : xa_c;
    const __half* wp  = layer ? wt1  : wt0;
    const float* dmod = layer ? d1 : d0;
    const float* bias = layer ? bias1 : bias0;
    const float* nsc  = layer ? ns1 : ns0;
    const float* noise= layer ? noise1 : noise0;

    // wait on producers
    if (layer) {
        if (tid == 0) {
            volatile int* fl = (volatile int*)g_flag;
            int lo = (yt > 0) ? yt - 1 : 0;
            int hi = (yt < 31) ? yt + 1 : 31;
            for (int yy = lo; yy <= hi; ++yy) {
                int fi = (b << 5) + yy;
                while (fl[fi] < 8) __nanosleep(200);
            }
        }
    } else {
        if (tid == 0) {
            volatile int* fl = (volatile int*)g_upflag;
            int lo = (y0 > 0) ? y0 - 1 : 0;
            int hi = (y0 + 2 < 63) ? y0 + 2 : 63;
            for (int yy = lo; yy <= hi; ++yy) {
                int fi = (b << 6) + yy;
                while (fl[fi] == 0) __nanosleep(100);
            }
        }
    }
    __syncthreads();
    __threadfence();

    float acc[2][8][4] = {};

    const int a_row = lane & 15;
    const int a_chalf = (lane >> 4) << 4;
    const int xl = ((lane >> 4) << 3) + (lane & 7);
    const int khalf = ((lane >> 3) & 1) << 4;

    stage_input_full(ib, xin, b, y0, 0, tid);
    stage_w(wb, 0, wp, o0, 0, 0, tid);
    CP_COMMIT();

    for (int s = 0; s < 72; ++s) {
        const int ic = s / 9;
        const int tap = s - ic * 9;

        CP_WAIT0();
        __syncthreads();

        int ns = s + 1;
        if (ns < 72) {
            int nic = ns / 9;
            stage_w(wb, ns & 1, wp, o0, ns - nic * 9, nic << 6, tid);
        }
        CP_COMMIT();

        const int ky = tap / 3, kx = tap - ky * 3;
        const int cellrow = (nwp + ky) * 66 + kx + xl;
        const uint32_t ws = wb + (s & 1) * W_STAGE;

        #pragma unroll
        for (int ks = 0; ks < 4; ++ks) {
            uint32_t ah[2][4];
            #pragma unroll
            for (int sm = 0; sm < 2; ++sm) {
                uint32_t off = (uint32_t)((mw*32 + sm*16 + a_row)*128
                                          + ks*32 + a_chalf);
                off ^= (off >> 3) & 0x70;
                ldsm_x4(ah[sm], ws + off);
            }
            uint32_t bh[4][4];
            #pragma unroll
            for (int sp = 0; sp < 4; ++sp) {
                uint32_t off = (uint32_t)((cellrow + sp*16)*128
                                          + ks*32 + khalf);
                off ^= (off >> 3) & 0x70;
                ldsm_x4(bh[sp], ib + off);
            }
            #pragma unroll
            for (int sm = 0; sm < 2; ++sm)
                #pragma unroll
                for (int sp = 0; sp < 4; ++sp)
                    #pragma unroll
                    for (int j = 0; j < 2; ++j)
                        mma_f16(acc[sm][sp*2 + j], ah[sm], &bh[sp][j*2]);
        }

        if (tap == 8 && ic < 7) {
            __syncthreads();
            stage_input_full(ib, xin, b, y0, (ic + 1) << 6, tid);
            CP_COMMIT();
        }
    }

    // ---- epilogue
    const int groupM = lane >> 2;
    const int groupN = 2 * (lane & 3);
    const float* np = noise + (size_t)b * PIX + y0 * 64;

    if (layer == 0) {
        __syncthreads();
        uint32_t* tp = (uint32_t*)dsm;        // [64 px-pairs][68] u32
        #pragma unroll
        for (int sm = 0; sm < 2; ++sm) {
            #pragma unroll
            for (int ro = 0; ro < 2; ++ro) {
                int ocl = mw * 32 + sm * 16 + groupM + ro * 8;
                int oc = o0 + ocl;
                float d  = dmod[b * Cn + oc];
                float bi = bias[oc];
                float nv = nsc[oc];
                float ps = s1[b * Cn + oc];
                #pragma unroll
                for (int sn = 0; sn < 8; ++sn) {
                    int px = nwp * 64 + sn * 8 + groupN;
                    float v0 = acc[sm][sn][ro * 2 + 0] * d + bi + nv * np[px + 0];
                    float v1 = acc[sm][sn][ro * 2 + 1] * d + bi + nv * np[px + 1];
                    v0 = ((v0 >= 0.f) ? v0 : 0.2f * v0) * ps;
                    v1 = ((v1 >= 0.f) ? v1 : 0.2f * v1) * ps;
                    uint32_t pk = (uint32_t)__half_as_ushort(__float2half_rn(v0))
                        | ((uint32_t)__half_as_ushort(__float2half_rn(v1)) << 16);
                    tp[(px >> 1) * 68 + ocl] = pk;
                }
            }
        }
        __syncthreads();
        {
            int p = tid;
            int yy = y0 + (p >> 6), xx = p & 63;
            uint32_t sel = (p & 1) ? 0x7632u : 0x5410u;
            size_t abase = (((size_t)b * PADHW + yy + 1) * PADHW + xx + 1) * Cn + o0;
            uint4* dst = (uint4*)(xb_p + abase);
            const uint32_t* srcp = tp + (p >> 1) * 68;
            #pragma unroll
            for (int i = 0; i < 8; ++i) {
                dst[i] = make_uint4(
                    __byte_perm(srcp[i*8+0], srcp[i*8+1], sel),
                    __byte_perm(srcp[i*8+2], srcp[i*8+3], sel),
                    __byte_perm(srcp[i*8+4], srcp[i*8+5], sel),
                    __byte_perm(srcp[i*8+6], srcp[i*8+7], sel));
            }
        }
        __threadfence();
        __syncthreads();
        if (tid == 0) atomicAdd(&g_flag[nt], 1);
    } else {
        const int yrow = y0 + nwp;
        float P[3][16];
        #pragma unroll
        for (int r = 0; r < 3; ++r)
            #pragma unroll
            for (int j = 0; j < 16; ++j) P[r][j] = 0.f;

        #pragma unroll
        for (int sm = 0; sm < 2; ++sm) {
            #pragma unroll
            for (int ro = 0; ro < 2; ++ro) {
                int ocl = mw * 32 + sm * 16 + groupM + ro * 8;
                int oc = o0 + ocl;
                float d  = dmod[b * Cn + oc];
                float bi = bias[oc];
                float nv = nsc[oc];
                float s2v = s2[b * Cn + oc];
                float w3[3];
                #pragma unroll
                for (int r = 0; r < 3; ++r) w3[r] = rgbW[r * Cn + oc] * s2v;
                float* dst = outX + ((size_t)(b * Cn + oc) * 64 + yrow) * 64;
                #pragma unroll
                for (int sn = 0; sn < 8; ++sn) {
                    int x = sn * 8 + groupN;
                    int px = nwp * 64 + x;
                    float v0 = acc[sm][sn][ro * 2 + 0] * d + bi + nv * np[px + 0];
                    float v1 = acc[sm][sn][ro * 2 + 1] * d + bi + nv * np[px + 1];
                    v0 = (v0 >= 0.f) ? v0 : 0.2f * v0;
                    v1 = (v1 >= 0.f) ? v1 : 0.2f * v1;
                    *(float2*)(dst + x) = make_float2(v0, v1);
                    #pragma unroll
                    for (int r = 0; r < 3; ++r) {
                        P[r][sn * 2 + 0] += w3[r] * v0;
                        P[r][sn * 2 + 1] += w3[r] * v1;
                    }
                }
            }
        }
        #pragma unroll
        for (int off = 4; off <= 16; off <<= 1)
            #pragma unroll
            for (int r = 0; r < 3; ++r)
                #pragma unroll
                for (int j = 0; j < 16; ++j)
                    P[r][j] += __shfl_xor_sync(0xffffffffu, P[r][j], off);

        __syncthreads();
        float* rgbsm = (float*)dsm;
        if (groupM == 0) {
            float* wr = rgbsm + (((mw * 2 + nwp) * 4) + (lane & 3)) * 48;
            #pragma unroll
            for (int r = 0; r < 3; ++r)
                #pragma unroll
                for (int j = 0; j < 16; ++j) wr[r * 16 + j] = P[r][j];
        }
        __syncthreads();
        #pragma unroll
        for (int k = 0; k < 3; ++k) {
            int o = tid * 3 + k;
            int j = o & 15;
            int q = o >> 4;
            int r = q % 3; q /= 3;
            int gN = q & 3;
            int nw2 = q >> 2;
            float v = rgbsm[((0 + nw2) * 4 + gN) * 48 + r * 16 + j]
                    + rgbsm[((2 + nw2) * 4 + gN) * 48 + r * 16 + j];
            int px = nw2 * 64 + (j >> 1) * 8 + gN * 2 + (j & 1);
            int y = y0 + (px >> 6), x = px & 63;
            atomicAdd(outRGB + ((size_t)(b * 3 + r) * 64 + y) * 64 + x, v);
        }
    }
}

// ---------------------------------------------------------------------------
extern "C" void kernel_launch(void* const* d_in, const int* in_sizes, int n_in,
                              void* d_out, int out_size)
{
    const float* maps   = (const float*)d_in[0];
    const float* w      = (const float*)d_in[1];
    const float* rgb    = (const float*)d_in[2];
    const float* noise0 = (const float*)d_in[3];
    const float* noise1 = (const float*)d_in[4];
    const float* w0     = (const float*)d_in[5];
    const float* b0     = (const float*)d_in[6];
    const float* sW0    = (const float*)d_in[7];
    const float* sB0    = (const float*)d_in[8];
    const float* ns0    = (const float*)d_in[9];
    const float* w1     = (const float*)d_in[10];
    const float* b1     = (const float*)d_in[11];
    const float* sW1    = (const float*)d_in[12];
    const float* sB1    = (const float*)d_in[13];
    const float* ns1    = (const float*)d_in[14];
    const float* rgbW   = (const float*)d_in[15];
    const float* rgbB   = (const float*)d_in[16];
    const float* rgbSW  = (const float*)d_in[17];
    const float* rgbSB  = (const float*)d_in[18];

    float* out    = (float*)d_out;
    float* outRGB = out;
    float* outX   = out + RGBELEMS;

    __half *xa, *xb, *wt0, *wt1;
    float *d0p, *d1p, *s1p, *s2p;
    cudaGetSymbolAddress((void**)&xa, g_xa);
    cudaGetSymbolAddress((void**)&xb, g_xb);
    cudaGetSymbolAddress((void**)&wt0, g_wt0);
    cudaGetSymbolAddress((void**)&wt1, g_wt1);
    cudaGetSymbolAddress((void**)&d0p, g_d0);
    cudaGetSymbolAddress((void**)&d1p, g_d1);
    cudaGetSymbolAddress((void**)&s1p, g_s1);
    cudaGetSymbolAddress((void**)&s2p, g_s2);

    cudaFuncSetAttribute(k_mega, cudaFuncAttributeMaxDynamicSharedMemorySize, DSMEM);

    k_prep<<<(N_PREP + 255) / 256, 256>>>(w, sW0, sB0, sW1, sB1, rgbSW, rgbSB,
                                          w0, w1, rgb, rgbB, outRGB);
    k_demod<<<(2 * Bn * Cn + 255) / 256, 256>>>();

    k_mega<<<4608, 128, DSMEM>>>(maps, xa, xa, xb, xb, wt0, wt1,
                                 d0p, d1p, b0, b1, ns0, ns1,
                                 noise0, noise1, s1p, outX,
                                 rgbW, s2p, outRGB);
}

// round 17
// speedup vs baseline: 1.0765x; 1.0765x over previous
#include <cuda_runtime.h>
#include <cuda_fp16.h>
#include <cstdint>
#include <math.h>

// ===========================================================================
// StyleGAN2 block. R17: R15 structure (k_up separate; conv0+conv1 in one
// 4096-block kernel with flag deps; to_rgb fused in layer-1 epilogue)
// + restructured k_prep (wprep+wsq fused, coalesced, 1 thread per (l,o,i)).
// Output: [rgb_out (8*3*64*64)] ++ [x (8*512*64*64)], fp32.
// ===========================================================================

#define Bn 8
#define Cn 512
#define HIN 32
#define PIX 4096
#define XELEMS (Bn*Cn*PIX)
#define RGBELEMS (Bn*3*PIX)
#define PADHW 66
#define PADCELLS (PADHW*PADHW)

// smem layout (bytes from dynamic smem base)
#define I_BUF   33792            // 4 rows * 66 cells * 128B (fp16), single
#define W_BASE  33792
#define W_STAGE 8192             // 64oc x 128B
#define N_WSTG  2
#define DSMEM   (W_BASE + N_WSTG*W_STAGE)   // 50176

// ---------------- device scratch (allocation-free rule) -------------------
__device__ __half g_xa[(size_t)Bn*PADCELLS*Cn];
__device__ __half g_xb[(size_t)Bn*PADCELLS*Cn];
__device__ __half g_wt0[9*Cn*Cn];
__device__ __half g_wt1[9*Cn*Cn];
__device__ float g_s0[Bn*Cn], g_s1[Bn*Cn], g_s2[Bn*Cn];
__device__ float g_d0[Bn*Cn], g_d1[Bn*Cn];
__device__ float g_wsq0[Cn*Cn], g_wsq1[Cn*Cn];
__device__ int   g_flag[256];    // octiles completed per (b*32 + ytile)

// ---------------- helpers --------------------------------------------------
__device__ __forceinline__ uint32_t smem_u32(const void* p) {
    uint32_t a;
    asm("{ .reg .u64 t; cvta.to.shared.u64 t, %1; cvt.u32.u64 %0, t; }"
        : "=r"(a) : "l"(p));
    return a;
}
__device__ __forceinline__ void ldsm_x4(uint32_t* r, uint32_t addr) {
    asm volatile("ldmatrix.sync.aligned.m8n8.x4.shared.b16 {%0,%1,%2,%3}, [%4];"
        : "=r"(r[0]), "=r"(r[1]), "=r"(r[2]), "=r"(r[3]) : "r"(addr));
}
__device__ __forceinline__ void mma_f16(float* c, const uint32_t* a,
                                        const uint32_t* b) {
    asm volatile(
        "mma.sync.aligned.m16n8k16.row.col.f32.f16.f16.f32 "
        "{%0,%1,%2,%3},{%4,%5,%6,%7},{%8,%9},{%0,%1,%2,%3};"
        : "+f"(c[0]), "+f"(c[1]), "+f"(c[2]), "+f"(c[3])
        : "r"(a[0]), "r"(a[1]), "r"(a[2]), "r"(a[3]), "r"(b[0]), "r"(b[1]));
}
__device__ __forceinline__ void cp16(uint32_t dst, const void* src) {
    asm volatile("cp.async.cg.shared.global [%0], [%1], 16;"
        :: "r"(dst), "l"(src));
}
#define CP_COMMIT() asm volatile("cp.async.commit_group;" ::: "memory")
#define CP_WAIT0()  asm volatile("cp.async.wait_group 0;" ::: "memory")

// ---------------------------------------------------------------------------
// fused prep: styles + (wprep+wsq fused) + halo-zero + outRGB init + flags
// ---------------------------------------------------------------------------
#define N_STY (3*Bn*Cn)                // 12288
#define N_WPQ (2*Cn*Cn)                // 524288: one thread per (layer,o,i)
#define N_ZER (Bn*260*256)             // 532480
#define N_RGBI RGBELEMS                // 98304
#define N_FLG 256
#define N_PREP (N_STY + N_WPQ + N_ZER + N_RGBI + N_FLG)

__global__ void k_prep(const float* __restrict__ w,
                       const float* __restrict__ sW0, const float* __restrict__ sB0,
                       const float* __restrict__ sW1, const float* __restrict__ sB1,
                       const float* __restrict__ sW2, const float* __restrict__ sB2,
                       const float* __restrict__ w0, const float* __restrict__ w1,
                       const float* __restrict__ rgb, const float* __restrict__ rgbB,
                       float* __restrict__ outRGB)
{
    int idx = blockIdx.x * blockDim.x + threadIdx.x;
    if (idx < N_STY) {
        int which = idx / (Bn * Cn);
        int rem   = idx % (Bn * Cn);
        int b = rem / Cn, c = rem % Cn;
        const float* sW = (which == 0) ? sW0 : (which == 1) ? sW1 : sW2;
        const float* sB = (which == 0) ? sB0 : (which == 1) ? sB1 : sB2;
        const float* wr = w + b * Cn;
        const float* sr = sW + c * Cn;
        float acc = 0.f;
        #pragma unroll 8
        for (int k = 0; k < Cn; ++k) acc += wr[k] * sr[k];
        acc += sB[c];
        ((which == 0) ? g_s0 : (which == 1) ? g_s1 : g_s2)[b * Cn + c] = acc;
        return;
    }
    idx -= N_STY;
    if (idx < N_WPQ) {
        // one thread per (layer, o, i): 9 contiguous loads, wsq + 9 fp16 planes
        int layer = idx >> 18;              // / (Cn*Cn)
        int e = idx & (Cn * Cn - 1);        // o*Cn + i
        const float* W = layer ? w1 : w0;
        const float* p = W + (size_t)e * 9;
        float v[9];
        float a = 0.f;
        #pragma unroll
        for (int t = 0; t < 9; ++t) { v[t] = p[t]; a += v[t] * v[t]; }
        (layer ? g_wsq1 : g_wsq0)[e] = a;
        __half* wt = layer ? g_wt1 : g_wt0;
        #pragma unroll
        for (int t = 0; t < 9; ++t)
            wt[(size_t)t * (Cn * Cn) + e] = __float2half_rn(v[t]);
        return;
    }
    idx -= N_WPQ;
    if (idx < N_ZER) {
        int c2 = idx & 255;
        int cell = (idx >> 8) % 260;
        int b = (idx >> 8) / 260;
        int y, x;
        if (cell < 66)       { y = 0;  x = cell; }
        else if (cell < 132) { y = 65; x = cell - 66; }
        else { int r = cell - 132; y = 1 + (r & 63); x = (r >> 6) ? 65 : 0; }
        size_t a = ((((size_t)b * PADHW + y) * PADHW + x) * Cn) / 2 + c2;
        ((uint32_t*)g_xa)[a] = 0u;
        ((uint32_t*)g_xb)[a] = 0u;
        return;
    }
    idx -= N_ZER;
    if (idx < N_RGBI) {
        int X = idx & 63;
        int Y = (idx >> 6) & 63;
        int br = idx >> 12;
        int r = br % 3;
        int yl = (Y - 1) >> 1; int yu = yl + 1;
        float wyu = (Y & 1) ? 0.25f : 0.75f;
        yl = max(yl, 0); yu = min(yu, HIN - 1);
        int xl = (X - 1) >> 1; int xu = xl + 1;
        float wxu = (X & 1) ? 0.25f : 0.75f;
        xl = max(xl, 0); xu = min(xu, HIN - 1);
        const float* p = rgb + (size_t)br * (HIN * HIN);
        float up = (1.f - wyu) * ((1.f - wxu) * p[yl*HIN+xl] + wxu * p[yl*HIN+xu])
                 +         wyu * ((1.f - wxu) * p[yu*HIN+xl] + wxu * p[yu*HIN+xu]);
        outRGB[idx] = up + rgbB[r];
        return;
    }
    idx -= N_RGBI;
    if (idx < N_FLG) g_flag[idx] = 0;
}

__global__ void k_demod()
{
    int idx = blockIdx.x * blockDim.x + threadIdx.x;
    if (idx >= 2 * Bn * Cn) return;
    int which = idx / (Bn * Cn);
    int rem   = idx % (Bn * Cn);
    int b = rem / Cn, o = rem % Cn;
    const float* wsq = which ? g_wsq1 : g_wsq0;
    const float* s   = which ? g_s1 : g_s0;
    const float* wr = wsq + o * Cn;
    const float* sr = s + b * Cn;
    float acc = 0.f;
    #pragma unroll 8
    for (int k = 0; k < Cn; ++k) { float sv = sr[k]; acc += wr[k] * sv * sv; }
    (which ? g_d1 : g_d0)[b * Cn + o] = rsqrtf(acc + 1e-8f);
}

// ---------------------------------------------------------------------------
// upsample maps 2x bilinear, *s0, write padded HWC fp16 plane
// ---------------------------------------------------------------------------
__global__ void __launch_bounds__(256) k_up(const float* __restrict__ maps)
{
    __shared__ unsigned short tile[64 * 65];
    int bx = blockIdx.x;
    int b = bx >> 6, y = bx & 63;
    int tid = threadIdx.x;

    int yl = (y - 1) >> 1, yu = yl + 1;
    float wyu = (y & 1) ? 0.25f : 0.75f;
    yl = max(yl, 0); yu = min(yu, HIN - 1);

    for (int c0 = 0; c0 < Cn; c0 += 64) {
        #pragma unroll
        for (int k = 0; k < 16; ++k) {
            int e = tid + (k << 8);
            int c = e >> 6, x = e & 63;
            int xl = (x - 1) >> 1, xu = xl + 1;
            float wxu = (x & 1) ? 0.25f : 0.75f;
            xl = max(xl, 0); xu = min(xu, HIN - 1);
            const float* p = maps + (size_t)(b * Cn + c0 + c) * (HIN * HIN);
            float v = (1.f - wyu) * ((1.f - wxu) * p[yl*HIN+xl] + wxu * p[yl*HIN+xu])
                    +         wyu * ((1.f - wxu) * p[yu*HIN+xl] + wxu * p[yu*HIN+xu]);
            v *= g_s0[b * Cn + c0 + c];
            tile[c * 65 + x] = __half_as_ushort(__float2half_rn(v));
        }
        __syncthreads();
        #pragma unroll
        for (int k = 0; k < 16; ++k) {
            int e = tid + (k << 8);
            int x = e >> 6, c = e & 63;
            size_t a = (((size_t)b * PADHW + y + 1) * PADHW + x + 1) * Cn + c0 + c;
            g_xa[a] = __ushort_as_half(tile[c * 65 + x]);
        }
        __syncthreads();
    }
}

// ---------------------------------------------------------------------------
// conv staging (128 threads)
// ---------------------------------------------------------------------------
__device__ __forceinline__ void stage_w(
    uint32_t wbase, int stg, const __half* __restrict__ wp,
    int o0, int tap, int ic0, int tid)
{
    const uint32_t base = wbase + stg * W_STAGE;
    #pragma unroll
    for (int k = 0; k < 4; ++k) {
        int s = tid + (k << 7);
        int r = s >> 3, g = s & 7;
        const __half* src = wp + ((size_t)tap * Cn + o0 + r) * Cn + ic0 + g * 8;
        uint32_t off = (uint32_t)((r << 7) + (g << 4));
        off ^= (off >> 3) & 0x70;
        cp16(base + off, src);
    }
}

__device__ __forceinline__ void stage_input_full(
    uint32_t ibase, const __half* __restrict__ x,
    int b, int y0, int ic0, int tid)
{
    for (int idx = tid; idx < 2112; idx += 128) {
        int cell = idx >> 3, g = idx & 7;
        int r = cell / 66, xx = cell - r * 66;
        const __half* src = x
            + (((size_t)b * PADHW + y0 + r) * PADHW + xx) * Cn + ic0 + g * 8;
        uint32_t off = (uint32_t)((cell << 7) + (g << 4));
        off ^= (off >> 3) & 0x70;
        cp16(ibase + off, src);
    }
}

// ---------------------------------------------------------------------------
// fused dual-conv: blocks [0,2048) = layer0 tiles, [2048,4096) = layer1.
// Tile = 64oc x 128px (2 rows); 128 threads, 4 warps 2m x 2n; 4 CTAs/SM.
// ---------------------------------------------------------------------------
__global__ void __launch_bounds__(128, 4) k_conv_fused(
    const __half* __restrict__ xa,
    const __half* __restrict__ xb_c,
    __half*       __restrict__ xb_p,
    const __half* __restrict__ wt0, const __half* __restrict__ wt1,
    const float* __restrict__ d0,  const float* __restrict__ d1,
    const float* __restrict__ bias0, const float* __restrict__ bias1,
    const float* __restrict__ ns0, const float* __restrict__ ns1,
    const float* __restrict__ noise0, const float* __restrict__ noise1,
    const float* __restrict__ s1,
    float* __restrict__ outX,
    const float* __restrict__ rgbW,
    const float* __restrict__ s2,
    float* __restrict__ outRGB)
{
    extern __shared__ __align__(16) char dsm[];
    const uint32_t ib = smem_u32(dsm);
    const uint32_t wb = ib + W_BASE;
    const int tid = threadIdx.x;
    const int lane = tid & 31, wid = tid >> 5;
    const int mw = wid >> 1, nwp = wid & 1;

    const int vt = blockIdx.x;
    const int layer = vt >> 11;
    const int t = vt & 2047;
    const int o0 = (t & 7) * 64;
    const int nt = t >> 3;                 // b*32 + ytile
    const int b  = nt >> 5;
    const int yt = nt & 31;
    const int y0 = yt * 2;

    const __half* xin = layer ? xb_c : xa;
    const __half* wp  = layer ? wt1  : wt0;
    const float* dmod = layer ? d1 : d0;
    const float* bias = layer ? bias1 : bias0;
    const float* nsc  = layer ? ns1 : ns0;
    const float* noise= layer ? noise1 : noise0;

    if (layer) {
        if (tid == 0) {
            volatile int* fl = (volatile int*)g_flag;
            int lo = (yt > 0) ? yt - 1 : 0;
            int hi = (yt < 31) ? yt + 1 : 31;
            for (int yy = lo; yy <= hi; ++yy) {
                int fi = (b << 5) + yy;
                while (fl[fi] < 8) __nanosleep(200);
            }
        }
        __syncthreads();
        __threadfence();
    }

    float acc[2][8][4] = {};

    const int a_row = lane & 15;
    const int a_chalf = (lane >> 4) << 4;
    const int xl = ((lane >> 4) << 3) + (lane & 7);
    const int khalf = ((lane >> 3) & 1) << 4;

    stage_input_full(ib, xin, b, y0, 0, tid);
    stage_w(wb, 0, wp, o0, 0, 0, tid);
    CP_COMMIT();

    for (int s = 0; s < 72; ++s) {
        const int ic = s / 9;
        const int tap = s - ic * 9;

        CP_WAIT0();
        __syncthreads();

        int ns = s + 1;
        if (ns < 72) {
            int nic = ns / 9;
            stage_w(wb, ns & 1, wp, o0, ns - nic * 9, nic << 6, tid);
        }
        CP_COMMIT();

        const int ky = tap / 3, kx = tap - ky * 3;
        const int cellrow = (nwp + ky) * 66 + kx + xl;
        const uint32_t ws = wb + (s & 1) * W_STAGE;

        #pragma unroll
        for (int ks = 0; ks < 4; ++ks) {
            uint32_t ah[2][4];
            #pragma unroll
            for (int sm = 0; sm < 2; ++sm) {
                uint32_t off = (uint32_t)((mw*32 + sm*16 + a_row)*128
                                          + ks*32 + a_chalf);
                off ^= (off >> 3) & 0x70;
                ldsm_x4(ah[sm], ws + off);
            }
            uint32_t bh[4][4];
            #pragma unroll
            for (int sp = 0; sp < 4; ++sp) {
                uint32_t off = (uint32_t)((cellrow + sp*16)*128
                                          + ks*32 + khalf);
                off ^= (off >> 3) & 0x70;
                ldsm_x4(bh[sp], ib + off);
            }
            #pragma unroll
            for (int sm = 0; sm < 2; ++sm)
                #pragma unroll
                for (int sp = 0; sp < 4; ++sp)
                    #pragma unroll
                    for (int j = 0; j < 2; ++j)
                        mma_f16(acc[sm][sp*2 + j], ah[sm], &bh[sp][j*2]);
        }

        if (tap == 8 && ic < 7) {
            __syncthreads();
            stage_input_full(ib, xin, b, y0, (ic + 1) << 6, tid);
            CP_COMMIT();
        }
    }

    // ---- epilogue. c-frag: e0,e1=(row, col,col+1) e2,e3=(row+8, ..)
    const int groupM = lane >> 2;
    const int groupN = 2 * (lane & 3);
    const float* np = noise + (size_t)b * PIX + y0 * 64;

    if (layer == 0) {
        __syncthreads();
        uint32_t* tp = (uint32_t*)dsm;        // [64 px-pairs][68] u32
        #pragma unroll
        for (int sm = 0; sm < 2; ++sm) {
            #pragma unroll
            for (int ro = 0; ro < 2; ++ro) {
                int ocl = mw * 32 + sm * 16 + groupM + ro * 8;
                int oc = o0 + ocl;
                float d  = dmod[b * Cn + oc];
                float bi = bias[oc];
                float nv = nsc[oc];
                float ps = s1[b * Cn + oc];
                #pragma unroll
                for (int sn = 0; sn < 8; ++sn) {
                    int px = nwp * 64 + sn * 8 + groupN;
                    float v0 = acc[sm][sn][ro * 2 + 0] * d + bi + nv * np[px + 0];
                    float v1 = acc[sm][sn][ro * 2 + 1] * d + bi + nv * np[px + 1];
                    v0 = ((v0 >= 0.f) ? v0 : 0.2f * v0) * ps;
                    v1 = ((v1 >= 0.f) ? v1 : 0.2f * v1) * ps;
                    uint32_t pk = (uint32_t)__half_as_ushort(__float2half_rn(v0))
                        | ((uint32_t)__half_as_ushort(__float2half_rn(v1)) << 16);
                    tp[(px >> 1) * 68 + ocl] = pk;
                }
            }
        }
        __syncthreads();
        {
            int p = tid;
            int yy = y0 + (p >> 6), xx = p & 63;
            uint32_t sel = (p & 1) ? 0x7632u : 0x5410u;
            size_t abase = (((size_t)b * PADHW + yy + 1) * PADHW + xx + 1) * Cn + o0;
            uint4* dst = (uint4*)(xb_p + abase);
            const uint32_t* srcp = tp + (p >> 1) * 68;
            #pragma unroll
            for (int i = 0; i < 8; ++i) {
                dst[i] = make_uint4(
                    __byte_perm(srcp[i*8+0], srcp[i*8+1], sel),
                    __byte_perm(srcp[i*8+2], srcp[i*8+3], sel),
                    __byte_perm(srcp[i*8+4], srcp[i*8+5], sel),
                    __byte_perm(srcp[i*8+6], srcp[i*8+7], sel));
            }
        }
        __threadfence();
        __syncthreads();
        if (tid == 0) atomicAdd(&g_flag[nt], 1);
    } else {
        const int yrow = y0 + nwp;
        float P[3][16];
        #pragma unroll
        for (int r = 0; r < 3; ++r)
            #pragma unroll
            for (int j = 0; j < 16; ++j) P[r][j] = 0.f;

        #pragma unroll
        for (int sm = 0; sm < 2; ++sm) {
            #pragma unroll
            for (int ro = 0; ro < 2; ++ro) {
                int ocl = mw * 32 + sm * 16 + groupM + ro * 8;
                int oc = o0 + ocl;
                float d  = dmod[b * Cn + oc];
                float bi = bias[oc];
                float nv = nsc[oc];
                float s2v = s2[b * Cn + oc];
                float w3[3];
                #pragma unroll
                for (int r = 0; r < 3; ++r) w3[r] = rgbW[r * Cn + oc] * s2v;
                float* dst = outX + ((size_t)(b * Cn + oc) * 64 + yrow) * 64;
                #pragma unroll
                for (int sn = 0; sn < 8; ++sn) {
                    int x = sn * 8 + groupN;
                    int px = nwp * 64 + x;
                    float v0 = acc[sm][sn][ro * 2 + 0] * d + bi + nv * np[px + 0];
                    float v1 = acc[sm][sn][ro * 2 + 1] * d + bi + nv * np[px + 1];
                    v0 = (v0 >= 0.f) ? v0 : 0.2f * v0;
                    v1 = (v1 >= 0.f) ? v1 : 0.2f * v1;
                    *(float2*)(dst + x) = make_float2(v0, v1);
                    #pragma unroll
                    for (int r = 0; r < 3; ++r) {
                        P[r][sn * 2 + 0] += w3[r] * v0;
                        P[r][sn * 2 + 1] += w3[r] * v1;
                    }
                }
            }
        }
        #pragma unroll
        for (int off = 4; off <= 16; off <<= 1)
            #pragma unroll
            for (int r = 0; r < 3; ++r)
                #pragma unroll
                for (int j = 0; j < 16; ++j)
                    P[r][j] += __shfl_xor_sync(0xffffffffu, P[r][j], off);

        __syncthreads();
        float* rgbsm = (float*)dsm;
        if (groupM == 0) {
            float* wr = rgbsm + (((mw * 2 + nwp) * 4) + (lane & 3)) * 48;
            #pragma unroll
            for (int r = 0; r < 3; ++r)
                #pragma unroll
                for (int j = 0; j < 16; ++j) wr[r * 16 + j] = P[r][j];
        }
        __syncthreads();
        #pragma unroll
        for (int k = 0; k < 3; ++k) {
            int o = tid * 3 + k;
            int j = o & 15;
            int q = o >> 4;
            int r = q % 3; q /= 3;
            int gN = q & 3;
            int nw2 = q >> 2;
            float v = rgbsm[((0 + nw2) * 4 + gN) * 48 + r * 16 + j]
                    + rgbsm[((2 + nw2) * 4 + gN) * 48 + r * 16 + j];
            int px = nw2 * 64 + (j >> 1) * 8 + gN * 2 + (j & 1);
            int y = y0 + (px >> 6), x = px & 63;
            atomicAdd(outRGB + ((size_t)(b * 3 + r) * 64 + y) * 64 + x, v);
        }
    }
}

// ---------------------------------------------------------------------------
extern "C" void kernel_launch(void* const* d_in, const int* in_sizes, int n_in,
                              void* d_out, int out_size)
{
    const float* maps   = (const float*)d_in[0];
    const float* w      = (const float*)d_in[1];
    const float* rgb    = (const float*)d_in[2];
    const float* noise0 = (const float*)d_in[3];
    const float* noise1 = (const float*)d_in[4];
    const float* w0     = (const float*)d_in[5];
    const float* b0     = (const float*)d_in[6];
    const float* sW0    = (const float*)d_in[7];
    const float* sB0    = (const float*)d_in[8];
    const float* ns0    = (const float*)d_in[9];
    const float* w1     = (const float*)d_in[10];
    const float* b1     = (const float*)d_in[11];
    const float* sW1    = (const float*)d_in[12];
    const float* sB1    = (const float*)d_in[13];
    const float* ns1    = (const float*)d_in[14];
    const float* rgbW   = (const float*)d_in[15];
    const float* rgbB   = (const float*)d_in[16];
    const float* rgbSW  = (const float*)d_in[17];
    const float* rgbSB  = (const float*)d_in[18];

    float* out    = (float*)d_out;
    float* outRGB = out;
    float* outX   = out + RGBELEMS;

    __half *xa, *xb, *wt0, *wt1;
    float *d0p, *d1p, *s1p, *s2p;
    cudaGetSymbolAddress((void**)&xa, g_xa);
    cudaGetSymbolAddress((void**)&xb, g_xb);
    cudaGetSymbolAddress((void**)&wt0, g_wt0);
    cudaGetSymbolAddress((void**)&wt1, g_wt1);
    cudaGetSymbolAddress((void**)&d0p, g_d0);
    cudaGetSymbolAddress((void**)&d1p, g_d1);
    cudaGetSymbolAddress((void**)&s1p, g_s1);
    cudaGetSymbolAddress((void**)&s2p, g_s2);

    cudaFuncSetAttribute(k_conv_fused, cudaFuncAttributeMaxDynamicSharedMemorySize, DSMEM);

    k_prep<<<(N_PREP + 255) / 256, 256>>>(w, sW0, sB0, sW1, sB1, rgbSW, rgbSB,
                                          w0, w1, rgb, rgbB, outRGB);
    k_demod<<<(2 * Bn * Cn + 255) / 256, 256>>>();
    k_up<<<Bn * 64, 256>>>(maps);

    k_conv_fused<<<4096, 128, DSMEM>>>(xa, xb, xb, wt0, wt1,
                                       d0p, d1p, b0, b1, ns0, ns1,
                                       noise0, noise1, s1p, outX,
                                       rgbW, s2p, outRGB);
}